// round 14
// baseline (speedup 1.0000x reference)
#include <cuda_runtime.h>
#include <cuda_bf16.h>
#include <math.h>

// ---------------- problem constants ----------------
#define BATCH   2
#define SEQ     2048
#define DMODEL  1024
#define NHEADS  16
#define DHEAD   64
#define DFF     4096
#define MROWS   (BATCH * SEQ)        // 4096
#define LN_EPS  1e-5f

// ---------------- scratch (device globals; no allocations allowed) --------
__device__ float g_h   [MROWS * DMODEL];
__device__ float g_qkv [MROWS * 3 * DMODEL];
__device__ float g_attn[MROWS * DMODEL];
__device__ float g_x2  [MROWS * DMODEL];
__device__ float g_ffn [MROWS * DFF];

// ====================== LayerNorm =========================================
__global__ __launch_bounds__(256)
void ln_kernel(const float* __restrict__ x, const float* __restrict__ g,
               const float* __restrict__ b, float* __restrict__ y)
{
    const int row = blockIdx.x;
    const int tid = threadIdx.x;
    const float4 xv = ((const float4*)(x + (size_t)row * DMODEL))[tid];

    float s  = xv.x + xv.y + xv.z + xv.w;
    float ss = xv.x*xv.x + xv.y*xv.y + xv.z*xv.z + xv.w*xv.w;

    #pragma unroll
    for (int o = 16; o > 0; o >>= 1) {
        s  += __shfl_xor_sync(0xffffffffu, s,  o);
        ss += __shfl_xor_sync(0xffffffffu, ss, o);
    }
    __shared__ float shs[8], shss[8];
    const int lane = tid & 31, warp = tid >> 5;
    if (lane == 0) { shs[warp] = s; shss[warp] = ss; }
    __syncthreads();
    if (warp == 0) {
        s  = shs[lane & 7];
        ss = shss[lane & 7];
        #pragma unroll
        for (int o = 4; o > 0; o >>= 1) {
            s  += __shfl_xor_sync(0xffffffffu, s,  o);
            ss += __shfl_xor_sync(0xffffffffu, ss, o);
        }
        if (lane == 0) { shs[0] = s; shss[0] = ss; }
    }
    __syncthreads();
    const float mean = shs[0] * (1.0f / DMODEL);
    const float var  = shss[0] * (1.0f / DMODEL) - mean * mean;
    const float inv  = rsqrtf(var + LN_EPS);

    const float4 gv = ((const float4*)g)[tid];
    const float4 bv = ((const float4*)b)[tid];
    float4 out;
    out.x = (xv.x - mean) * inv * gv.x + bv.x;
    out.y = (xv.y - mean) * inv * gv.y + bv.y;
    out.z = (xv.z - mean) * inv * gv.z + bv.z;
    out.w = (xv.w - mean) * inv * gv.w + bv.w;
    ((float4*)(y + (size_t)row * DMODEL))[tid] = out;
}

// ====================== bf16x3 tensor-core GEMM ===========================
// C[M,N] = A[M,K] @ B[K,N] + bias (+GELU / +residual), fp32 in/out.
// Each fp32 operand split hi/lo bf16; D = Ah*Bh + Al*Bh + Ah*Bl (fp32 accum).
// CTA tile 128x128, BK=16, 8 warps (4 M x 2 N), warp tile 32x64,
// mma.sync.m16n8k16 (2 M-tiles x 8 N-tiles per warp).

#define SW 136   // u32 row stride in smem: bank = (8*k2 + idx) % 32, conflict-free

__device__ __forceinline__ float gelu_exact(float v) {
    return 0.5f * v * (1.0f + erff(v * 0.70710678118654752f));
}

__device__ __forceinline__ void split2(float x0, float x1,
                                       unsigned int& h, unsigned int& l)
{
    __nv_bfloat16 h0 = __float2bfloat16_rn(x0);
    __nv_bfloat16 h1 = __float2bfloat16_rn(x1);
    __nv_bfloat16 l0 = __float2bfloat16_rn(x0 - __bfloat162float(h0));
    __nv_bfloat16 l1 = __float2bfloat16_rn(x1 - __bfloat162float(h1));
    h = ((unsigned int)__bfloat16_as_ushort(h1) << 16) | __bfloat16_as_ushort(h0);
    l = ((unsigned int)__bfloat16_as_ushort(l1) << 16) | __bfloat16_as_ushort(l0);
}

#define MMA16816(d, a, b)                                                      \
    asm volatile("mma.sync.aligned.m16n8k16.row.col.f32.bf16.bf16.f32 "        \
                 "{%0,%1,%2,%3}, {%4,%5,%6,%7}, {%8,%9}, {%0,%1,%2,%3};"       \
                 : "+f"(d[0]), "+f"(d[1]), "+f"(d[2]), "+f"(d[3])              \
                 : "r"(a[0]), "r"(a[1]), "r"(a[2]), "r"(a[3]),                 \
                   "r"(b[0]), "r"(b[1]))

__device__ __forceinline__ void load_afrag(unsigned int a[2][4],
                                           const unsigned int* As,
                                           int wm, int gid, int tg)
{
    #pragma unroll
    for (int mi = 0; mi < 2; mi++) {
        const int m = wm + mi * 16 + gid;
        a[mi][0] = As[tg * SW + m];
        a[mi][1] = As[tg * SW + m + 8];
        a[mi][2] = As[(tg + 4) * SW + m];
        a[mi][3] = As[(tg + 4) * SW + m + 8];
    }
}

__device__ __forceinline__ void load_bfrag(unsigned int b[8][2],
                                           const unsigned int* Bs,
                                           int wn, int gid, int tg)
{
    #pragma unroll
    for (int ni = 0; ni < 8; ni++) {
        const int n = wn + ni * 8 + gid;
        b[ni][0] = Bs[tg * SW + n];
        b[ni][1] = Bs[(tg + 4) * SW + n];
    }
}

template<int EPI>   // 0=bias, 1=bias+gelu, 2=bias+residual
__global__ __launch_bounds__(256, 2)
void gemm_bf16x3(const float* __restrict__ A, const float* __restrict__ B,
                 const float* __restrict__ bias, const float* __restrict__ res,
                 float* __restrict__ C, int M, int N, int K)
{
    __shared__ unsigned int smAh[2][8 * SW];
    __shared__ unsigned int smAl[2][8 * SW];
    __shared__ unsigned int smBh[2][8 * SW];
    __shared__ unsigned int smBl[2][8 * SW];

    const int tid  = threadIdx.x;
    const int bm   = blockIdx.y * 128;
    const int bn   = blockIdx.x * 128;
    const int lane = tid & 31, wid = tid >> 5;
    const int wm   = (wid & 3) * 32;
    const int wn   = (wid >> 2) * 64;
    const int gid  = lane >> 2, tg = lane & 3;

    // staging index precompute
    const int idx0 = 2 * tid,      idx1 = 2 * tid + 1;
    const int am0  = idx0 >> 2,    ak0  = (idx0 & 3) * 4;
    const int am1  = idx1 >> 2,    ak1  = (idx1 & 3) * 4;
    const int br   = tid >> 5,     bn4  = (tid & 31) * 4;

    float acc[2][8][4];
    #pragma unroll
    for (int mi = 0; mi < 2; mi++)
        #pragma unroll
        for (int ni = 0; ni < 8; ni++)
            #pragma unroll
            for (int j = 0; j < 4; j++) acc[mi][ni][j] = 0.0f;

    const int KT = K >> 4;
    float4 sa0, sa1, sb0, sb1;

    // ---- stage loader / smem writer --------------------------------------
    auto load_stage = [&](int kt) {
        sa0 = *(const float4*)&A[(size_t)(bm + am0) * K + kt * 16 + ak0];
        sa1 = *(const float4*)&A[(size_t)(bm + am1) * K + kt * 16 + ak1];
        sb0 = *(const float4*)&B[(size_t)(kt * 16 + 2 * br)     * N + bn + bn4];
        sb1 = *(const float4*)&B[(size_t)(kt * 16 + 2 * br + 1) * N + bn + bn4];
    };
    auto store_stage = [&](int buf) {
        unsigned int* Ah = smAh[buf]; unsigned int* Al = smAl[buf];
        unsigned int* Bh = smBh[buf]; unsigned int* Bl = smBl[buf];
        unsigned int h, l;
        {   // A element 0: covers k = ak0..ak0+3 (k2 = ak0/2, ak0/2+1)
            const int k2 = ak0 >> 1;
            split2(sa0.x, sa0.y, h, l); Ah[k2 * SW + am0] = h;       Al[k2 * SW + am0] = l;
            split2(sa0.z, sa0.w, h, l); Ah[(k2 + 1) * SW + am0] = h; Al[(k2 + 1) * SW + am0] = l;
        }
        {
            const int k2 = ak1 >> 1;
            split2(sa1.x, sa1.y, h, l); Ah[k2 * SW + am1] = h;       Al[k2 * SW + am1] = l;
            split2(sa1.z, sa1.w, h, l); Ah[(k2 + 1) * SW + am1] = h; Al[(k2 + 1) * SW + am1] = l;
        }
        uint4 H, L;
        split2(sb0.x, sb1.x, H.x, L.x);
        split2(sb0.y, sb1.y, H.y, L.y);
        split2(sb0.z, sb1.z, H.z, L.z);
        split2(sb0.w, sb1.w, H.w, L.w);
        *(uint4*)&Bh[br * SW + bn4] = H;
        *(uint4*)&Bl[br * SW + bn4] = L;
    };

    load_stage(0);
    store_stage(0);
    __syncthreads();

    for (int kt = 0; kt < KT; kt++) {
        const int cur = kt & 1;
        if (kt + 1 < KT) load_stage(kt + 1);

        unsigned int ah[2][4], al[2][4], b[8][2];
        load_afrag(ah, smAh[cur], wm, gid, tg);
        load_afrag(al, smAl[cur], wm, gid, tg);
        load_bfrag(b,  smBh[cur], wn, gid, tg);
        #pragma unroll
        for (int mi = 0; mi < 2; mi++)
            #pragma unroll
            for (int ni = 0; ni < 8; ni++) MMA16816(acc[mi][ni], ah[mi], b[ni]);
        #pragma unroll
        for (int mi = 0; mi < 2; mi++)
            #pragma unroll
            for (int ni = 0; ni < 8; ni++) MMA16816(acc[mi][ni], al[mi], b[ni]);
        load_bfrag(b, smBl[cur], wn, gid, tg);
        #pragma unroll
        for (int mi = 0; mi < 2; mi++)
            #pragma unroll
            for (int ni = 0; ni < 8; ni++) MMA16816(acc[mi][ni], ah[mi], b[ni]);

        if (kt + 1 < KT) store_stage(cur ^ 1);
        __syncthreads();
    }

    // ---- epilogue --------------------------------------------------------
    #pragma unroll
    for (int mi = 0; mi < 2; mi++) {
        const int r0 = bm + wm + mi * 16 + gid;
        #pragma unroll
        for (int ni = 0; ni < 8; ni++) {
            const int col = bn + wn + ni * 8 + tg * 2;
            const float2 bi = *(const float2*)&bias[col];
            float2 v0, v1;
            v0.x = acc[mi][ni][0] + bi.x; v0.y = acc[mi][ni][1] + bi.y;
            v1.x = acc[mi][ni][2] + bi.x; v1.y = acc[mi][ni][3] + bi.y;
            if (EPI == 1) {
                v0.x = gelu_exact(v0.x); v0.y = gelu_exact(v0.y);
                v1.x = gelu_exact(v1.x); v1.y = gelu_exact(v1.y);
            }
            if (EPI == 2) {
                const float2 ra = *(const float2*)&res[(size_t)r0 * N + col];
                const float2 rb = *(const float2*)&res[(size_t)(r0 + 8) * N + col];
                v0.x += ra.x; v0.y += ra.y;
                v1.x += rb.x; v1.y += rb.y;
            }
            *(float2*)&C[(size_t)r0 * N + col]       = v0;
            *(float2*)&C[(size_t)(r0 + 8) * N + col] = v1;
        }
    }
}

// ====================== Causal attention (flash-style) ====================
#define QT 128
#define KT_ATT 64
__global__ __launch_bounds__(128)
void attn_kernel(const float* __restrict__ qkv, float* __restrict__ o_out)
{
    const int bh = blockIdx.y;
    const int b  = bh >> 4;
    const int h  = bh & 15;
    const int q0 = blockIdx.x * QT;
    const int tid = threadIdx.x;
    const int q = q0 + tid;

    const float* base = qkv + (size_t)b * SEQ * (3 * DMODEL);

    float qreg[DHEAD];
    {
        const float4* qp = (const float4*)(base + (size_t)q * (3 * DMODEL) + h * DHEAD);
        #pragma unroll
        for (int i = 0; i < DHEAD / 4; i++) {
            const float4 t = qp[i];
            qreg[4*i+0] = t.x; qreg[4*i+1] = t.y; qreg[4*i+2] = t.z; qreg[4*i+3] = t.w;
        }
    }

    float o[DHEAD];
    #pragma unroll
    for (int d = 0; d < DHEAD; d++) o[d] = 0.0f;
    float m = -1e30f, l = 0.0f;

    __shared__ float Ks[KT_ATT][DHEAD];
    __shared__ float Vs[KT_ATT][DHEAD];

    const int ktiles = (q0 + QT) / KT_ATT;
    for (int kt = 0; kt < ktiles; kt++) {
        const int k0 = kt * KT_ATT;
        __syncthreads();
        #pragma unroll
        for (int r = 0; r < 8; r++) {
            const int idx = r * 128 + tid;
            const int kr  = idx >> 4;
            const int c4  = (idx & 15) * 4;
            const size_t roff = (size_t)(k0 + kr) * (3 * DMODEL) + h * DHEAD + c4;
            *(float4*)&Ks[kr][c4] = *(const float4*)(base + roff + DMODEL);
            *(float4*)&Vs[kr][c4] = *(const float4*)(base + roff + 2 * DMODEL);
        }
        __syncthreads();

        const int kmax = min(KT_ATT, q - k0 + 1);
        for (int k = 0; k < kmax; k++) {
            float s = 0.0f;
            #pragma unroll
            for (int d = 0; d < DHEAD; d += 4) {
                const float4 kv = *(const float4*)&Ks[k][d];
                s += qreg[d+0]*kv.x + qreg[d+1]*kv.y + qreg[d+2]*kv.z + qreg[d+3]*kv.w;
            }
            s *= 0.125f;
            if (s > m) {
                const float c = __expf(m - s);
                l *= c;
                #pragma unroll
                for (int d = 0; d < DHEAD; d++) o[d] *= c;
                m = s;
            }
            const float p = __expf(s - m);
            l += p;
            #pragma unroll
            for (int d = 0; d < DHEAD; d += 4) {
                const float4 vv = *(const float4*)&Vs[k][d];
                o[d+0] += p * vv.x; o[d+1] += p * vv.y;
                o[d+2] += p * vv.z; o[d+3] += p * vv.w;
            }
        }
    }

    const float inv = 1.0f / l;
    float* op = o_out + ((size_t)(b * SEQ + q)) * DMODEL + h * DHEAD;
    #pragma unroll
    for (int d = 0; d < DHEAD; d += 4) {
        float4 r;
        r.x = o[d+0]*inv; r.y = o[d+1]*inv; r.z = o[d+2]*inv; r.w = o[d+3]*inv;
        *(float4*)&op[d] = r;
    }
}

// ====================== launch ============================================
extern "C" void kernel_launch(void* const* d_in, const int* in_sizes, int n_in,
                              void* d_out, int out_size)
{
    const float* x     = (const float*)d_in[0];
    const float* ln1_g = (const float*)d_in[2];
    const float* ln1_b = (const float*)d_in[3];
    const float* qkv_w = (const float*)d_in[4];
    const float* qkv_b = (const float*)d_in[5];
    const float* out_w = (const float*)d_in[6];
    const float* out_b = (const float*)d_in[7];
    const float* ln2_g = (const float*)d_in[8];
    const float* ln2_b = (const float*)d_in[9];
    const float* w1    = (const float*)d_in[10];
    const float* b1    = (const float*)d_in[11];
    const float* w2    = (const float*)d_in[12];
    const float* b2    = (const float*)d_in[13];
    float* out = (float*)d_out;

    float *p_h, *p_qkv, *p_attn, *p_x2, *p_ffn;
    cudaGetSymbolAddress((void**)&p_h,    g_h);
    cudaGetSymbolAddress((void**)&p_qkv,  g_qkv);
    cudaGetSymbolAddress((void**)&p_attn, g_attn);
    cudaGetSymbolAddress((void**)&p_x2,   g_x2);
    cudaGetSymbolAddress((void**)&p_ffn,  g_ffn);

    // 1. h = LN1(x)
    ln_kernel<<<MROWS, 256>>>(x, ln1_g, ln1_b, p_h);

    // 2. qkv = h @ qkv_w + qkv_b      [4096 x 3072 x 1024]
    gemm_bf16x3<0><<<dim3(3 * DMODEL / 128, MROWS / 128), 256>>>(
        p_h, qkv_w, qkv_b, nullptr, p_qkv, MROWS, 3 * DMODEL, DMODEL);

    // 3. attention
    attn_kernel<<<dim3(SEQ / QT, BATCH * NHEADS), 128>>>(p_qkv, p_attn);

    // 4. x2 = x + attn @ out_w + out_b   [4096 x 1024 x 1024]
    gemm_bf16x3<2><<<dim3(DMODEL / 128, MROWS / 128), 256>>>(
        p_attn, out_w, out_b, x, p_x2, MROWS, DMODEL, DMODEL);

    // 5. h = LN2(x2)
    ln_kernel<<<MROWS, 256>>>(p_x2, ln2_g, ln2_b, p_h);

    // 6. ffn = gelu(h @ w1 + b1)      [4096 x 4096 x 1024]
    gemm_bf16x3<1><<<dim3(DFF / 128, MROWS / 128), 256>>>(
        p_h, w1, b1, nullptr, p_ffn, MROWS, DFF, DMODEL);

    // 7. out = x2 + ffn @ w2 + b2     [4096 x 1024 x 4096]
    gemm_bf16x3<2><<<dim3(DMODEL / 128, MROWS / 128), 256>>>(
        p_ffn, w2, b2, p_x2, out, MROWS, DMODEL, DFF);
}

// round 15
// speedup vs baseline: 1.0073x; 1.0073x over previous
#include <cuda_runtime.h>
#include <cuda_bf16.h>
#include <math.h>

// ---------------- problem constants ----------------
#define BATCH   2
#define SEQ     2048
#define DMODEL  1024
#define NHEADS  16
#define DHEAD   64
#define DFF     4096
#define MROWS   (BATCH * SEQ)        // 4096
#define LN_EPS  1e-5f

// ---------------- scratch (device globals; no allocations allowed) --------
__device__ float g_h   [MROWS * DMODEL];
__device__ float g_qkv [MROWS * 3 * DMODEL];
__device__ float g_attn[MROWS * DMODEL];
__device__ float g_x2  [MROWS * DMODEL];
__device__ float g_ffn [MROWS * DFF];

// ====================== LayerNorm =========================================
__global__ __launch_bounds__(256)
void ln_kernel(const float* __restrict__ x, const float* __restrict__ g,
               const float* __restrict__ b, float* __restrict__ y)
{
    const int row = blockIdx.x;
    const int tid = threadIdx.x;
    const float4 xv = ((const float4*)(x + (size_t)row * DMODEL))[tid];

    float s  = xv.x + xv.y + xv.z + xv.w;
    float ss = xv.x*xv.x + xv.y*xv.y + xv.z*xv.z + xv.w*xv.w;

    #pragma unroll
    for (int o = 16; o > 0; o >>= 1) {
        s  += __shfl_xor_sync(0xffffffffu, s,  o);
        ss += __shfl_xor_sync(0xffffffffu, ss, o);
    }
    __shared__ float shs[8], shss[8];
    const int lane = tid & 31, warp = tid >> 5;
    if (lane == 0) { shs[warp] = s; shss[warp] = ss; }
    __syncthreads();
    if (warp == 0) {
        s  = shs[lane & 7];
        ss = shss[lane & 7];
        #pragma unroll
        for (int o = 4; o > 0; o >>= 1) {
            s  += __shfl_xor_sync(0xffffffffu, s,  o);
            ss += __shfl_xor_sync(0xffffffffu, ss, o);
        }
        if (lane == 0) { shs[0] = s; shss[0] = ss; }
    }
    __syncthreads();
    const float mean = shs[0] * (1.0f / DMODEL);
    const float var  = shss[0] * (1.0f / DMODEL) - mean * mean;
    const float inv  = rsqrtf(var + LN_EPS);

    const float4 gv = ((const float4*)g)[tid];
    const float4 bv = ((const float4*)b)[tid];
    float4 out;
    out.x = (xv.x - mean) * inv * gv.x + bv.x;
    out.y = (xv.y - mean) * inv * gv.y + bv.y;
    out.z = (xv.z - mean) * inv * gv.z + bv.z;
    out.w = (xv.w - mean) * inv * gv.w + bv.w;
    ((float4*)(y + (size_t)row * DMODEL))[tid] = out;
}

// ====================== bf16x3 tensor-core GEMM ===========================
// C[M,N] = A[M,K] @ B[K,N] + bias (+GELU / +residual), fp32 in/out.
// Each fp32 operand split hi/lo bf16; D = Ah*Bh + Al*Bh + Ah*Bl (fp32 accum).
// CTA tile 128x128, BK=16, 8 warps (4 M x 2 N), warp tile 32x64,
// mma.sync.m16n8k16 (2 M-tiles x 8 N-tiles per warp).

#define SW 136   // u32 row stride in smem: bank = (8*k2 + idx) % 32, conflict-free

__device__ __forceinline__ float gelu_exact(float v) {
    return 0.5f * v * (1.0f + erff(v * 0.70710678118654752f));
}

__device__ __forceinline__ void split2(float x0, float x1,
                                       unsigned int& h, unsigned int& l)
{
    __nv_bfloat16 h0 = __float2bfloat16_rn(x0);
    __nv_bfloat16 h1 = __float2bfloat16_rn(x1);
    __nv_bfloat16 l0 = __float2bfloat16_rn(x0 - __bfloat162float(h0));
    __nv_bfloat16 l1 = __float2bfloat16_rn(x1 - __bfloat162float(h1));
    h = ((unsigned int)__bfloat16_as_ushort(h1) << 16) | __bfloat16_as_ushort(h0);
    l = ((unsigned int)__bfloat16_as_ushort(l1) << 16) | __bfloat16_as_ushort(l0);
}

#define MMA16816(d, a, b)                                                      \
    asm volatile("mma.sync.aligned.m16n8k16.row.col.f32.bf16.bf16.f32 "        \
                 "{%0,%1,%2,%3}, {%4,%5,%6,%7}, {%8,%9}, {%0,%1,%2,%3};"       \
                 : "+f"(d[0]), "+f"(d[1]), "+f"(d[2]), "+f"(d[3])              \
                 : "r"(a[0]), "r"(a[1]), "r"(a[2]), "r"(a[3]),                 \
                   "r"(b[0]), "r"(b[1]))

__device__ __forceinline__ void load_afrag(unsigned int a[2][4],
                                           const unsigned int* As,
                                           int wm, int gid, int tg)
{
    #pragma unroll
    for (int mi = 0; mi < 2; mi++) {
        const int m = wm + mi * 16 + gid;
        a[mi][0] = As[tg * SW + m];
        a[mi][1] = As[tg * SW + m + 8];
        a[mi][2] = As[(tg + 4) * SW + m];
        a[mi][3] = As[(tg + 4) * SW + m + 8];
    }
}

__device__ __forceinline__ void load_bfrag(unsigned int b[8][2],
                                           const unsigned int* Bs,
                                           int wn, int gid, int tg)
{
    #pragma unroll
    for (int ni = 0; ni < 8; ni++) {
        const int n = wn + ni * 8 + gid;
        b[ni][0] = Bs[tg * SW + n];
        b[ni][1] = Bs[(tg + 4) * SW + n];
    }
}

template<int EPI>   // 0=bias, 1=bias+gelu, 2=bias+residual
__global__ __launch_bounds__(256, 2)
void gemm_bf16x3(const float* __restrict__ A, const float* __restrict__ B,
                 const float* __restrict__ bias, const float* __restrict__ res,
                 float* __restrict__ C, int M, int N, int K)
{
    __shared__ unsigned int smAh[2][8 * SW];
    __shared__ unsigned int smAl[2][8 * SW];
    __shared__ unsigned int smBh[2][8 * SW];
    __shared__ unsigned int smBl[2][8 * SW];

    const int tid  = threadIdx.x;
    const int bm   = blockIdx.y * 128;
    const int bn   = blockIdx.x * 128;
    const int lane = tid & 31, wid = tid >> 5;
    const int wm   = (wid & 3) * 32;
    const int wn   = (wid >> 2) * 64;
    const int gid  = lane >> 2, tg = lane & 3;

    // staging index precompute
    const int idx0 = 2 * tid,      idx1 = 2 * tid + 1;
    const int am0  = idx0 >> 2,    ak0  = (idx0 & 3) * 4;
    const int am1  = idx1 >> 2,    ak1  = (idx1 & 3) * 4;
    const int br   = tid >> 5,     bn4  = (tid & 31) * 4;

    float acc[2][8][4];
    #pragma unroll
    for (int mi = 0; mi < 2; mi++)
        #pragma unroll
        for (int ni = 0; ni < 8; ni++)
            #pragma unroll
            for (int j = 0; j < 4; j++) acc[mi][ni][j] = 0.0f;

    const int KT = K >> 4;
    float4 sa0, sa1, sb0, sb1;

    // ---- stage loader / smem writer --------------------------------------
    auto load_stage = [&](int kt) {
        sa0 = *(const float4*)&A[(size_t)(bm + am0) * K + kt * 16 + ak0];
        sa1 = *(const float4*)&A[(size_t)(bm + am1) * K + kt * 16 + ak1];
        sb0 = *(const float4*)&B[(size_t)(kt * 16 + 2 * br)     * N + bn + bn4];
        sb1 = *(const float4*)&B[(size_t)(kt * 16 + 2 * br + 1) * N + bn + bn4];
    };
    auto store_stage = [&](int buf) {
        unsigned int* Ah = smAh[buf]; unsigned int* Al = smAl[buf];
        unsigned int* Bh = smBh[buf]; unsigned int* Bl = smBl[buf];
        unsigned int h, l;
        {   // A element 0: covers k = ak0..ak0+3 (k2 = ak0/2, ak0/2+1)
            const int k2 = ak0 >> 1;
            split2(sa0.x, sa0.y, h, l); Ah[k2 * SW + am0] = h;       Al[k2 * SW + am0] = l;
            split2(sa0.z, sa0.w, h, l); Ah[(k2 + 1) * SW + am0] = h; Al[(k2 + 1) * SW + am0] = l;
        }
        {
            const int k2 = ak1 >> 1;
            split2(sa1.x, sa1.y, h, l); Ah[k2 * SW + am1] = h;       Al[k2 * SW + am1] = l;
            split2(sa1.z, sa1.w, h, l); Ah[(k2 + 1) * SW + am1] = h; Al[(k2 + 1) * SW + am1] = l;
        }
        uint4 H, L;
        split2(sb0.x, sb1.x, H.x, L.x);
        split2(sb0.y, sb1.y, H.y, L.y);
        split2(sb0.z, sb1.z, H.z, L.z);
        split2(sb0.w, sb1.w, H.w, L.w);
        *(uint4*)&Bh[br * SW + bn4] = H;
        *(uint4*)&Bl[br * SW + bn4] = L;
    };

    load_stage(0);
    store_stage(0);
    __syncthreads();

    for (int kt = 0; kt < KT; kt++) {
        const int cur = kt & 1;
        if (kt + 1 < KT) load_stage(kt + 1);

        unsigned int ah[2][4], al[2][4], b[8][2];
        load_afrag(ah, smAh[cur], wm, gid, tg);
        load_afrag(al, smAl[cur], wm, gid, tg);
        load_bfrag(b,  smBh[cur], wn, gid, tg);
        #pragma unroll
        for (int mi = 0; mi < 2; mi++)
            #pragma unroll
            for (int ni = 0; ni < 8; ni++) MMA16816(acc[mi][ni], ah[mi], b[ni]);
        #pragma unroll
        for (int mi = 0; mi < 2; mi++)
            #pragma unroll
            for (int ni = 0; ni < 8; ni++) MMA16816(acc[mi][ni], al[mi], b[ni]);
        load_bfrag(b, smBl[cur], wn, gid, tg);
        #pragma unroll
        for (int mi = 0; mi < 2; mi++)
            #pragma unroll
            for (int ni = 0; ni < 8; ni++) MMA16816(acc[mi][ni], ah[mi], b[ni]);

        if (kt + 1 < KT) store_stage(cur ^ 1);
        __syncthreads();
    }

    // ---- epilogue --------------------------------------------------------
    #pragma unroll
    for (int mi = 0; mi < 2; mi++) {
        const int r0 = bm + wm + mi * 16 + gid;
        #pragma unroll
        for (int ni = 0; ni < 8; ni++) {
            const int col = bn + wn + ni * 8 + tg * 2;
            const float2 bi = *(const float2*)&bias[col];
            float2 v0, v1;
            v0.x = acc[mi][ni][0] + bi.x; v0.y = acc[mi][ni][1] + bi.y;
            v1.x = acc[mi][ni][2] + bi.x; v1.y = acc[mi][ni][3] + bi.y;
            if (EPI == 1) {
                v0.x = gelu_exact(v0.x); v0.y = gelu_exact(v0.y);
                v1.x = gelu_exact(v1.x); v1.y = gelu_exact(v1.y);
            }
            if (EPI == 2) {
                const float2 ra = *(const float2*)&res[(size_t)r0 * N + col];
                const float2 rb = *(const float2*)&res[(size_t)(r0 + 8) * N + col];
                v0.x += ra.x; v0.y += ra.y;
                v1.x += rb.x; v1.y += rb.y;
            }
            *(float2*)&C[(size_t)r0 * N + col]       = v0;
            *(float2*)&C[(size_t)(r0 + 8) * N + col] = v1;
        }
    }
}

// ====================== Causal attention (flash-style) ====================
#define QT 128
#define KT_ATT 64
__global__ __launch_bounds__(128)
void attn_kernel(const float* __restrict__ qkv, float* __restrict__ o_out)
{
    const int bh = blockIdx.y;
    const int b  = bh >> 4;
    const int h  = bh & 15;
    const int q0 = blockIdx.x * QT;
    const int tid = threadIdx.x;
    const int q = q0 + tid;

    const float* base = qkv + (size_t)b * SEQ * (3 * DMODEL);

    float qreg[DHEAD];
    {
        const float4* qp = (const float4*)(base + (size_t)q * (3 * DMODEL) + h * DHEAD);
        #pragma unroll
        for (int i = 0; i < DHEAD / 4; i++) {
            const float4 t = qp[i];
            qreg[4*i+0] = t.x; qreg[4*i+1] = t.y; qreg[4*i+2] = t.z; qreg[4*i+3] = t.w;
        }
    }

    float o[DHEAD];
    #pragma unroll
    for (int d = 0; d < DHEAD; d++) o[d] = 0.0f;
    float m = -1e30f, l = 0.0f;

    __shared__ float Ks[KT_ATT][DHEAD];
    __shared__ float Vs[KT_ATT][DHEAD];

    const int ktiles = (q0 + QT) / KT_ATT;
    for (int kt = 0; kt < ktiles; kt++) {
        const int k0 = kt * KT_ATT;
        __syncthreads();
        #pragma unroll
        for (int r = 0; r < 8; r++) {
            const int idx = r * 128 + tid;
            const int kr  = idx >> 4;
            const int c4  = (idx & 15) * 4;
            const size_t roff = (size_t)(k0 + kr) * (3 * DMODEL) + h * DHEAD + c4;
            *(float4*)&Ks[kr][c4] = *(const float4*)(base + roff + DMODEL);
            *(float4*)&Vs[kr][c4] = *(const float4*)(base + roff + 2 * DMODEL);
        }
        __syncthreads();

        const int kmax = min(KT_ATT, q - k0 + 1);
        for (int k = 0; k < kmax; k++) {
            float s = 0.0f;
            #pragma unroll
            for (int d = 0; d < DHEAD; d += 4) {
                const float4 kv = *(const float4*)&Ks[k][d];
                s += qreg[d+0]*kv.x + qreg[d+1]*kv.y + qreg[d+2]*kv.z + qreg[d+3]*kv.w;
            }
            s *= 0.125f;
            if (s > m) {
                const float c = __expf(m - s);
                l *= c;
                #pragma unroll
                for (int d = 0; d < DHEAD; d++) o[d] *= c;
                m = s;
            }
            const float p = __expf(s - m);
            l += p;
            #pragma unroll
            for (int d = 0; d < DHEAD; d += 4) {
                const float4 vv = *(const float4*)&Vs[k][d];
                o[d+0] += p * vv.x; o[d+1] += p * vv.y;
                o[d+2] += p * vv.z; o[d+3] += p * vv.w;
            }
        }
    }

    const float inv = 1.0f / l;
    float* op = o_out + ((size_t)(b * SEQ + q)) * DMODEL + h * DHEAD;
    #pragma unroll
    for (int d = 0; d < DHEAD; d += 4) {
        float4 r;
        r.x = o[d+0]*inv; r.y = o[d+1]*inv; r.z = o[d+2]*inv; r.w = o[d+3]*inv;
        *(float4*)&op[d] = r;
    }
}

// ====================== launch ============================================
extern "C" void kernel_launch(void* const* d_in, const int* in_sizes, int n_in,
                              void* d_out, int out_size)
{
    const float* x     = (const float*)d_in[0];
    const float* ln1_g = (const float*)d_in[2];
    const float* ln1_b = (const float*)d_in[3];
    const float* qkv_w = (const float*)d_in[4];
    const float* qkv_b = (const float*)d_in[5];
    const float* out_w = (const float*)d_in[6];
    const float* out_b = (const float*)d_in[7];
    const float* ln2_g = (const float*)d_in[8];
    const float* ln2_b = (const float*)d_in[9];
    const float* w1    = (const float*)d_in[10];
    const float* b1    = (const float*)d_in[11];
    const float* w2    = (const float*)d_in[12];
    const float* b2    = (const float*)d_in[13];
    float* out = (float*)d_out;

    float *p_h, *p_qkv, *p_attn, *p_x2, *p_ffn;
    cudaGetSymbolAddress((void**)&p_h,    g_h);
    cudaGetSymbolAddress((void**)&p_qkv,  g_qkv);
    cudaGetSymbolAddress((void**)&p_attn, g_attn);
    cudaGetSymbolAddress((void**)&p_x2,   g_x2);
    cudaGetSymbolAddress((void**)&p_ffn,  g_ffn);

    // 1. h = LN1(x)
    ln_kernel<<<MROWS, 256>>>(x, ln1_g, ln1_b, p_h);

    // 2. qkv = h @ qkv_w + qkv_b      [4096 x 3072 x 1024]
    gemm_bf16x3<0><<<dim3(3 * DMODEL / 128, MROWS / 128), 256>>>(
        p_h, qkv_w, qkv_b, nullptr, p_qkv, MROWS, 3 * DMODEL, DMODEL);

    // 3. attention
    attn_kernel<<<dim3(SEQ / QT, BATCH * NHEADS), 128>>>(p_qkv, p_attn);

    // 4. x2 = x + attn @ out_w + out_b   [4096 x 1024 x 1024]
    gemm_bf16x3<2><<<dim3(DMODEL / 128, MROWS / 128), 256>>>(
        p_attn, out_w, out_b, x, p_x2, MROWS, DMODEL, DMODEL);

    // 5. h = LN2(x2)
    ln_kernel<<<MROWS, 256>>>(p_x2, ln2_g, ln2_b, p_h);

    // 6. ffn = gelu(h @ w1 + b1)      [4096 x 4096 x 1024]
    gemm_bf16x3<1><<<dim3(DFF / 128, MROWS / 128), 256>>>(
        p_h, w1, b1, nullptr, p_ffn, MROWS, DFF, DMODEL);

    // 7. out = x2 + ffn @ w2 + b2     [4096 x 1024 x 4096]
    gemm_bf16x3<2><<<dim3(DMODEL / 128, MROWS / 128), 256>>>(
        p_ffn, w2, b2, p_x2, out, MROWS, DMODEL, DFF);
}

// round 16
// speedup vs baseline: 1.0106x; 1.0033x over previous
#include <cuda_runtime.h>
#include <cuda_bf16.h>
#include <math.h>

// ---------------- problem constants ----------------
#define BATCH   2
#define SEQ     2048
#define DMODEL  1024
#define NHEADS  16
#define DHEAD   64
#define DFF     4096
#define MROWS   (BATCH * SEQ)        // 4096
#define LN_EPS  1e-5f

// ---------------- scratch (device globals; no allocations allowed) --------
__device__ float g_h   [MROWS * DMODEL];
__device__ float g_qkv [MROWS * 3 * DMODEL];
__device__ float g_attn[MROWS * DMODEL];
__device__ float g_x2  [MROWS * DMODEL];
__device__ float g_ffn [MROWS * DFF];

// ====================== LayerNorm =========================================
__global__ __launch_bounds__(256)
void ln_kernel(const float* __restrict__ x, const float* __restrict__ g,
               const float* __restrict__ b, float* __restrict__ y)
{
    const int row = blockIdx.x;
    const int tid = threadIdx.x;
    const float4 xv = ((const float4*)(x + (size_t)row * DMODEL))[tid];

    float s  = xv.x + xv.y + xv.z + xv.w;
    float ss = xv.x*xv.x + xv.y*xv.y + xv.z*xv.z + xv.w*xv.w;

    #pragma unroll
    for (int o = 16; o > 0; o >>= 1) {
        s  += __shfl_xor_sync(0xffffffffu, s,  o);
        ss += __shfl_xor_sync(0xffffffffu, ss, o);
    }
    __shared__ float shs[8], shss[8];
    const int lane = tid & 31, warp = tid >> 5;
    if (lane == 0) { shs[warp] = s; shss[warp] = ss; }
    __syncthreads();
    if (warp == 0) {
        s  = shs[lane & 7];
        ss = shss[lane & 7];
        #pragma unroll
        for (int o = 4; o > 0; o >>= 1) {
            s  += __shfl_xor_sync(0xffffffffu, s,  o);
            ss += __shfl_xor_sync(0xffffffffu, ss, o);
        }
        if (lane == 0) { shs[0] = s; shss[0] = ss; }
    }
    __syncthreads();
    const float mean = shs[0] * (1.0f / DMODEL);
    const float var  = shss[0] * (1.0f / DMODEL) - mean * mean;
    const float inv  = rsqrtf(var + LN_EPS);

    const float4 gv = ((const float4*)g)[tid];
    const float4 bv = ((const float4*)b)[tid];
    float4 out;
    out.x = (xv.x - mean) * inv * gv.x + bv.x;
    out.y = (xv.y - mean) * inv * gv.y + bv.y;
    out.z = (xv.z - mean) * inv * gv.z + bv.z;
    out.w = (xv.w - mean) * inv * gv.w + bv.w;
    ((float4*)(y + (size_t)row * DMODEL))[tid] = out;
}

// ====================== bf16x3 tensor-core GEMM ===========================
// C[M,N] = A[M,K] @ B[K,N] + bias (+GELU / +residual), fp32 in/out.
// Each fp32 operand split hi/lo bf16; D = Ah*Bh + Al*Bh + Ah*Bl (fp32 accum).
// CTA tile 128x128, BK=16, 8 warps (4 M x 2 N), warp tile 32x64,
// mma.sync.m16n8k16 (2 M-tiles x 8 N-tiles per warp).

#define SW 136   // u32 row stride in smem: bank = (8*k2 + idx) % 32, conflict-free

__device__ __forceinline__ float gelu_exact(float v) {
    return 0.5f * v * (1.0f + erff(v * 0.70710678118654752f));
}

__device__ __forceinline__ void split2(float x0, float x1,
                                       unsigned int& h, unsigned int& l)
{
    __nv_bfloat16 h0 = __float2bfloat16_rn(x0);
    __nv_bfloat16 h1 = __float2bfloat16_rn(x1);
    __nv_bfloat16 l0 = __float2bfloat16_rn(x0 - __bfloat162float(h0));
    __nv_bfloat16 l1 = __float2bfloat16_rn(x1 - __bfloat162float(h1));
    h = ((unsigned int)__bfloat16_as_ushort(h1) << 16) | __bfloat16_as_ushort(h0);
    l = ((unsigned int)__bfloat16_as_ushort(l1) << 16) | __bfloat16_as_ushort(l0);
}

#define MMA16816(d, a, b)                                                      \
    asm volatile("mma.sync.aligned.m16n8k16.row.col.f32.bf16.bf16.f32 "        \
                 "{%0,%1,%2,%3}, {%4,%5,%6,%7}, {%8,%9}, {%0,%1,%2,%3};"       \
                 : "+f"(d[0]), "+f"(d[1]), "+f"(d[2]), "+f"(d[3])              \
                 : "r"(a[0]), "r"(a[1]), "r"(a[2]), "r"(a[3]),                 \
                   "r"(b[0]), "r"(b[1]))

__device__ __forceinline__ void load_afrag(unsigned int a[2][4],
                                           const unsigned int* As,
                                           int wm, int gid, int tg)
{
    #pragma unroll
    for (int mi = 0; mi < 2; mi++) {
        const int m = wm + mi * 16 + gid;
        a[mi][0] = As[tg * SW + m];
        a[mi][1] = As[tg * SW + m + 8];
        a[mi][2] = As[(tg + 4) * SW + m];
        a[mi][3] = As[(tg + 4) * SW + m + 8];
    }
}

__device__ __forceinline__ void load_bfrag(unsigned int b[8][2],
                                           const unsigned int* Bs,
                                           int wn, int gid, int tg)
{
    #pragma unroll
    for (int ni = 0; ni < 8; ni++) {
        const int n = wn + ni * 8 + gid;
        b[ni][0] = Bs[tg * SW + n];
        b[ni][1] = Bs[(tg + 4) * SW + n];
    }
}

template<int EPI>   // 0=bias, 1=bias+gelu, 2=bias+residual
__global__ __launch_bounds__(256, 2)
void gemm_bf16x3(const float* __restrict__ A, const float* __restrict__ B,
                 const float* __restrict__ bias, const float* __restrict__ res,
                 float* __restrict__ C, int M, int N, int K)
{
    __shared__ unsigned int smAh[2][8 * SW];
    __shared__ unsigned int smAl[2][8 * SW];
    __shared__ unsigned int smBh[2][8 * SW];
    __shared__ unsigned int smBl[2][8 * SW];

    const int tid  = threadIdx.x;
    const int bm   = blockIdx.y * 128;
    const int bn   = blockIdx.x * 128;
    const int lane = tid & 31, wid = tid >> 5;
    const int wm   = (wid & 3) * 32;
    const int wn   = (wid >> 2) * 64;
    const int gid  = lane >> 2, tg = lane & 3;

    // staging index precompute
    const int idx0 = 2 * tid,      idx1 = 2 * tid + 1;
    const int am0  = idx0 >> 2,    ak0  = (idx0 & 3) * 4;
    const int am1  = idx1 >> 2,    ak1  = (idx1 & 3) * 4;
    const int br   = tid >> 5,     bn4  = (tid & 31) * 4;

    float acc[2][8][4];
    #pragma unroll
    for (int mi = 0; mi < 2; mi++)
        #pragma unroll
        for (int ni = 0; ni < 8; ni++)
            #pragma unroll
            for (int j = 0; j < 4; j++) acc[mi][ni][j] = 0.0f;

    const int KT = K >> 4;
    float4 sa0, sa1, sb0, sb1;

    // ---- stage loader / smem writer --------------------------------------
    auto load_stage = [&](int kt) {
        sa0 = *(const float4*)&A[(size_t)(bm + am0) * K + kt * 16 + ak0];
        sa1 = *(const float4*)&A[(size_t)(bm + am1) * K + kt * 16 + ak1];
        sb0 = *(const float4*)&B[(size_t)(kt * 16 + 2 * br)     * N + bn + bn4];
        sb1 = *(const float4*)&B[(size_t)(kt * 16 + 2 * br + 1) * N + bn + bn4];
    };
    auto store_stage = [&](int buf) {
        unsigned int* Ah = smAh[buf]; unsigned int* Al = smAl[buf];
        unsigned int* Bh = smBh[buf]; unsigned int* Bl = smBl[buf];
        unsigned int h, l;
        {   // A element 0: covers k = ak0..ak0+3 (k2 = ak0/2, ak0/2+1)
            const int k2 = ak0 >> 1;
            split2(sa0.x, sa0.y, h, l); Ah[k2 * SW + am0] = h;       Al[k2 * SW + am0] = l;
            split2(sa0.z, sa0.w, h, l); Ah[(k2 + 1) * SW + am0] = h; Al[(k2 + 1) * SW + am0] = l;
        }
        {
            const int k2 = ak1 >> 1;
            split2(sa1.x, sa1.y, h, l); Ah[k2 * SW + am1] = h;       Al[k2 * SW + am1] = l;
            split2(sa1.z, sa1.w, h, l); Ah[(k2 + 1) * SW + am1] = h; Al[(k2 + 1) * SW + am1] = l;
        }
        uint4 H, L;
        split2(sb0.x, sb1.x, H.x, L.x);
        split2(sb0.y, sb1.y, H.y, L.y);
        split2(sb0.z, sb1.z, H.z, L.z);
        split2(sb0.w, sb1.w, H.w, L.w);
        *(uint4*)&Bh[br * SW + bn4] = H;
        *(uint4*)&Bl[br * SW + bn4] = L;
    };

    load_stage(0);
    store_stage(0);
    __syncthreads();

    for (int kt = 0; kt < KT; kt++) {
        const int cur = kt & 1;
        if (kt + 1 < KT) load_stage(kt + 1);

        unsigned int ah[2][4], al[2][4], b[8][2];
        load_afrag(ah, smAh[cur], wm, gid, tg);
        load_afrag(al, smAl[cur], wm, gid, tg);
        load_bfrag(b,  smBh[cur], wn, gid, tg);
        #pragma unroll
        for (int mi = 0; mi < 2; mi++)
            #pragma unroll
            for (int ni = 0; ni < 8; ni++) MMA16816(acc[mi][ni], ah[mi], b[ni]);
        #pragma unroll
        for (int mi = 0; mi < 2; mi++)
            #pragma unroll
            for (int ni = 0; ni < 8; ni++) MMA16816(acc[mi][ni], al[mi], b[ni]);
        load_bfrag(b, smBl[cur], wn, gid, tg);
        #pragma unroll
        for (int mi = 0; mi < 2; mi++)
            #pragma unroll
            for (int ni = 0; ni < 8; ni++) MMA16816(acc[mi][ni], ah[mi], b[ni]);

        if (kt + 1 < KT) store_stage(cur ^ 1);
        __syncthreads();
    }

    // ---- epilogue --------------------------------------------------------
    #pragma unroll
    for (int mi = 0; mi < 2; mi++) {
        const int r0 = bm + wm + mi * 16 + gid;
        #pragma unroll
        for (int ni = 0; ni < 8; ni++) {
            const int col = bn + wn + ni * 8 + tg * 2;
            const float2 bi = *(const float2*)&bias[col];
            float2 v0, v1;
            v0.x = acc[mi][ni][0] + bi.x; v0.y = acc[mi][ni][1] + bi.y;
            v1.x = acc[mi][ni][2] + bi.x; v1.y = acc[mi][ni][3] + bi.y;
            if (EPI == 1) {
                v0.x = gelu_exact(v0.x); v0.y = gelu_exact(v0.y);
                v1.x = gelu_exact(v1.x); v1.y = gelu_exact(v1.y);
            }
            if (EPI == 2) {
                const float2 ra = *(const float2*)&res[(size_t)r0 * N + col];
                const float2 rb = *(const float2*)&res[(size_t)(r0 + 8) * N + col];
                v0.x += ra.x; v0.y += ra.y;
                v1.x += rb.x; v1.y += rb.y;
            }
            *(float2*)&C[(size_t)r0 * N + col]       = v0;
            *(float2*)&C[(size_t)(r0 + 8) * N + col] = v1;
        }
    }
}

// ====================== Causal attention (flash-style) ====================
#define QT 128
#define KT_ATT 64
__global__ __launch_bounds__(128)
void attn_kernel(const float* __restrict__ qkv, float* __restrict__ o_out)
{
    const int bh = blockIdx.y;
    const int b  = bh >> 4;
    const int h  = bh & 15;
    const int q0 = blockIdx.x * QT;
    const int tid = threadIdx.x;
    const int q = q0 + tid;

    const float* base = qkv + (size_t)b * SEQ * (3 * DMODEL);

    float qreg[DHEAD];
    {
        const float4* qp = (const float4*)(base + (size_t)q * (3 * DMODEL) + h * DHEAD);
        #pragma unroll
        for (int i = 0; i < DHEAD / 4; i++) {
            const float4 t = qp[i];
            qreg[4*i+0] = t.x; qreg[4*i+1] = t.y; qreg[4*i+2] = t.z; qreg[4*i+3] = t.w;
        }
    }

    float o[DHEAD];
    #pragma unroll
    for (int d = 0; d < DHEAD; d++) o[d] = 0.0f;
    float m = -1e30f, l = 0.0f;

    __shared__ float Ks[KT_ATT][DHEAD];
    __shared__ float Vs[KT_ATT][DHEAD];

    const int ktiles = (q0 + QT) / KT_ATT;
    for (int kt = 0; kt < ktiles; kt++) {
        const int k0 = kt * KT_ATT;
        __syncthreads();
        #pragma unroll
        for (int r = 0; r < 8; r++) {
            const int idx = r * 128 + tid;
            const int kr  = idx >> 4;
            const int c4  = (idx & 15) * 4;
            const size_t roff = (size_t)(k0 + kr) * (3 * DMODEL) + h * DHEAD + c4;
            *(float4*)&Ks[kr][c4] = *(const float4*)(base + roff + DMODEL);
            *(float4*)&Vs[kr][c4] = *(const float4*)(base + roff + 2 * DMODEL);
        }
        __syncthreads();

        const int kmax = min(KT_ATT, q - k0 + 1);
        for (int k = 0; k < kmax; k++) {
            float s = 0.0f;
            #pragma unroll
            for (int d = 0; d < DHEAD; d += 4) {
                const float4 kv = *(const float4*)&Ks[k][d];
                s += qreg[d+0]*kv.x + qreg[d+1]*kv.y + qreg[d+2]*kv.z + qreg[d+3]*kv.w;
            }
            s *= 0.125f;
            if (s > m) {
                const float c = __expf(m - s);
                l *= c;
                #pragma unroll
                for (int d = 0; d < DHEAD; d++) o[d] *= c;
                m = s;
            }
            const float p = __expf(s - m);
            l += p;
            #pragma unroll
            for (int d = 0; d < DHEAD; d += 4) {
                const float4 vv = *(const float4*)&Vs[k][d];
                o[d+0] += p * vv.x; o[d+1] += p * vv.y;
                o[d+2] += p * vv.z; o[d+3] += p * vv.w;
            }
        }
    }

    const float inv = 1.0f / l;
    float* op = o_out + ((size_t)(b * SEQ + q)) * DMODEL + h * DHEAD;
    #pragma unroll
    for (int d = 0; d < DHEAD; d += 4) {
        float4 r;
        r.x = o[d+0]*inv; r.y = o[d+1]*inv; r.z = o[d+2]*inv; r.w = o[d+3]*inv;
        *(float4*)&op[d] = r;
    }
}

// ====================== launch ============================================
extern "C" void kernel_launch(void* const* d_in, const int* in_sizes, int n_in,
                              void* d_out, int out_size)
{
    const float* x     = (const float*)d_in[0];
    const float* ln1_g = (const float*)d_in[2];
    const float* ln1_b = (const float*)d_in[3];
    const float* qkv_w = (const float*)d_in[4];
    const float* qkv_b = (const float*)d_in[5];
    const float* out_w = (const float*)d_in[6];
    const float* out_b = (const float*)d_in[7];
    const float* ln2_g = (const float*)d_in[8];
    const float* ln2_b = (const float*)d_in[9];
    const float* w1    = (const float*)d_in[10];
    const float* b1    = (const float*)d_in[11];
    const float* w2    = (const float*)d_in[12];
    const float* b2    = (const float*)d_in[13];
    float* out = (float*)d_out;

    float *p_h, *p_qkv, *p_attn, *p_x2, *p_ffn;
    cudaGetSymbolAddress((void**)&p_h,    g_h);
    cudaGetSymbolAddress((void**)&p_qkv,  g_qkv);
    cudaGetSymbolAddress((void**)&p_attn, g_attn);
    cudaGetSymbolAddress((void**)&p_x2,   g_x2);
    cudaGetSymbolAddress((void**)&p_ffn,  g_ffn);

    // 1. h = LN1(x)
    ln_kernel<<<MROWS, 256>>>(x, ln1_g, ln1_b, p_h);

    // 2. qkv = h @ qkv_w + qkv_b      [4096 x 3072 x 1024]
    gemm_bf16x3<0><<<dim3(3 * DMODEL / 128, MROWS / 128), 256>>>(
        p_h, qkv_w, qkv_b, nullptr, p_qkv, MROWS, 3 * DMODEL, DMODEL);

    // 3. attention
    attn_kernel<<<dim3(SEQ / QT, BATCH * NHEADS), 128>>>(p_qkv, p_attn);

    // 4. x2 = x + attn @ out_w + out_b   [4096 x 1024 x 1024]
    gemm_bf16x3<2><<<dim3(DMODEL / 128, MROWS / 128), 256>>>(
        p_attn, out_w, out_b, x, p_x2, MROWS, DMODEL, DMODEL);

    // 5. h = LN2(x2)
    ln_kernel<<<MROWS, 256>>>(p_x2, ln2_g, ln2_b, p_h);

    // 6. ffn = gelu(h @ w1 + b1)      [4096 x 4096 x 1024]
    gemm_bf16x3<1><<<dim3(DFF / 128, MROWS / 128), 256>>>(
        p_h, w1, b1, nullptr, p_ffn, MROWS, DFF, DMODEL);

    // 7. out = x2 + ffn @ w2 + b2     [4096 x 1024 x 4096]
    gemm_bf16x3<2><<<dim3(DMODEL / 128, MROWS / 128), 256>>>(
        p_ffn, w2, b2, p_x2, out, MROWS, DMODEL, DFF);
}